// round 1
// baseline (speedup 1.0000x reference)
#include <cuda_runtime.h>
#include <math.h>

#define NN 10000
#define INF_ 512
#define OUTF 64
#define NWORDS 313   // ceil(10000/32)

// Scratch (static device globals — no allocations allowed)
__device__ float    g_Wh[NN * OUTF];      // h @ W
__device__ float    g_esrc[NN];           // Wh @ a_src
__device__ float4   g_jdata[NN];          // {edst, exp(edst), exp(0.2*edst), hub*0.01}
__device__ unsigned g_bits[NN * NWORDS];  // adj bitmask
__device__ float    g_maxd[NN];           // masked max of edst over row
__device__ float    g_Sp[NN];             // sum of exp(edst_j)    over adj & (e>0)
__device__ float    g_Sn[NN];             // sum of exp(.2*edst_j) over adj & (e<=0)
__device__ float4   g_rowp[NN];           // {-esrc, exp(esrc-m)/s, exp(.2esrc-m)/s, 0}

// ---------------------------------------------------------------------------
// K1: Wh = h @ W  (one warp per row), fused with e_src/e_dst dot products
// ---------------------------------------------------------------------------
__global__ void k_gemm(const float* __restrict__ h, const float* __restrict__ W,
                       const float* __restrict__ a_src, const float* __restrict__ a_dst,
                       const float* __restrict__ hub) {
    int warp = threadIdx.x >> 5, lane = threadIdx.x & 31;
    int row = blockIdx.x * 8 + warp;
    if (row >= NN) return;
    const float* hrow = h + (size_t)row * INF_;
    float ax = 0.f, ay = 0.f;
    int c2 = lane * 2;
    for (int kb = 0; kb < INF_; kb += 32) {
        float hk = hrow[kb + lane];
#pragma unroll
        for (int q = 0; q < 32; q++) {
            float hb = __shfl_sync(0xffffffffu, hk, q);
            float2 w = *reinterpret_cast<const float2*>(W + (size_t)(kb + q) * OUTF + c2);
            ax = fmaf(hb, w.x, ax);
            ay = fmaf(hb, w.y, ay);
        }
    }
    float2 o; o.x = ax; o.y = ay;
    *reinterpret_cast<float2*>(g_Wh + (size_t)row * OUTF + c2) = o;

    // fused edge logits: e_src[row] = Wh[row,:]·a_src, e_dst likewise
    float s = ax * a_src[c2] + ay * a_src[c2 + 1];
    float d = ax * a_dst[c2] + ay * a_dst[c2 + 1];
#pragma unroll
    for (int o2 = 16; o2; o2 >>= 1) {
        s += __shfl_xor_sync(0xffffffffu, s, o2);
        d += __shfl_xor_sync(0xffffffffu, d, o2);
    }
    if (lane == 0) {
        g_esrc[row] = s;
        float4 jd;
        jd.x = d;
        jd.y = expf(d);
        jd.z = expf(0.2f * d);
        jd.w = hub[row] * 0.01f;
        g_jdata[row] = jd;
    }
}

// ---------------------------------------------------------------------------
// K2: single pass over adj (400MB, DRAM-bound). Per block: 8 rows x all j.
// Produces: bitmask, masked max(edst), Sp, Sn per row.
// ---------------------------------------------------------------------------
__global__ void k_scan(const int* __restrict__ adj) {
    int t = threadIdx.x;
    int warp = t >> 5;
    int r0 = blockIdx.x * 8;
    float md[8], sp[8], sn[8], ns[8];
#pragma unroll
    for (int r = 0; r < 8; r++) {
        md[r] = -3.0e38f; sp[r] = 0.f; sn[r] = 0.f;
        ns[r] = -g_esrc[r0 + r];
    }
    for (int jb = 0; jb < NN; jb += 256) {
        int j = jb + t;
        bool valid = j < NN;
        float ed = 0.f, bp = 0.f, bn = 0.f;
        if (valid) { float4 jd = g_jdata[j]; ed = jd.x; bp = jd.y; bn = jd.z; }
#pragma unroll
        for (int r = 0; r < 8; r++) {
            int a = valid ? adj[(size_t)(r0 + r) * NN + j] : 0;
            bool on = a > 0;
            unsigned bm = __ballot_sync(0xffffffffu, on);
            if ((t & 31) == 0 && (jb + warp * 32) < NN)
                g_bits[(size_t)(r0 + r) * NWORDS + (jb >> 5) + warp] = bm;
            if (on) {
                md[r] = fmaxf(md[r], ed);
                if (ed > ns[r]) sp[r] += bp; else sn[r] += bn;
            }
        }
    }
    __shared__ float smax[8][8], ssp[8][8], ssn[8][8];
#pragma unroll
    for (int r = 0; r < 8; r++) {
        float a = md[r], b = sp[r], c = sn[r];
#pragma unroll
        for (int o = 16; o; o >>= 1) {
            a = fmaxf(a, __shfl_xor_sync(0xffffffffu, a, o));
            b += __shfl_xor_sync(0xffffffffu, b, o);
            c += __shfl_xor_sync(0xffffffffu, c, o);
        }
        if ((t & 31) == 0) { smax[r][warp] = a; ssp[r][warp] = b; ssn[r][warp] = c; }
    }
    __syncthreads();
    if (t < 8) {
        float a = smax[t][0], b = ssp[t][0], c = ssn[t][0];
#pragma unroll
        for (int w = 1; w < 8; w++) {
            a = fmaxf(a, smax[t][w]); b += ssp[t][w]; c += ssn[t][w];
        }
        g_maxd[r0 + t] = a; g_Sp[r0 + t] = b; g_Sn[r0 + t] = c;
    }
}

// ---------------------------------------------------------------------------
// K3: per-row softmax finalize (10000 threads)
// m = leaky(esrc + maxd);  s = exp(esrc-m)*Sp + exp(.2esrc-m)*Sn
// ---------------------------------------------------------------------------
__global__ void k_row() {
    int i = blockIdx.x * 256 + threadIdx.x;
    if (i >= NN) return;
    float es = g_esrc[i];
    float x = es + g_maxd[i];
    float m = x > 0.f ? x : 0.2f * x;
    float cp = expf(es - m), cn = expf(0.2f * es - m);
    float s = cp * g_Sp[i] + cn * g_Sn[i];
    float inv = 1.0f / s;
    float4 rp; rp.x = -es; rp.y = cp * inv; rp.z = cn * inv; rp.w = 0.f;
    g_rowp[i] = rp;
}

// ---------------------------------------------------------------------------
// K4: out[i,:] = ELU( sum_j relu(p_ij/s_i - hub_j*T) * Wh[j,:] )
// Block tile: 16 rows x 64 cols. Per 128-j chunk: compute pruned weights into
// smem + per-rowgroup nonzero bitmaps (warp-uniform), then sparse FMA.
// ---------------------------------------------------------------------------
__global__ void k_agg(float* __restrict__ out) {
    __shared__ float w_s[16][128];
    __shared__ unsigned nz_s[4][4];
    __shared__ float4 rp_s[16];
    int t = threadIdx.x;
    int r0 = blockIdx.x * 16;
    if (t < 16) rp_s[t] = g_rowp[r0 + t];
    int rg = t >> 6;   // rowgroup 0..3  (uniform per warp-pair)
    int c = t & 63;    // output column
    float acc0 = 0.f, acc1 = 0.f, acc2 = 0.f, acc3 = 0.f;

    for (int jb = 0; jb < NN; jb += 128) {
        __syncthreads();                       // prev accumulate done with w_s/nz_s
        if (t < 16) nz_s[t >> 2][t & 3] = 0u;
        __syncthreads();
        // ---- compute pruned weights + nonzero ballots ----
#pragma unroll
        for (int e = 0; e < 8; e++) {
            int idx = e * 256 + t;
            int rl = idx >> 7;                 // local row 0..15 (uniform per warp)
            int jj = idx & 127;                // jj contiguous per warp (32-aligned)
            int j = jb + jj;
            float w = 0.f;
            if (j < NN) {
                unsigned word = g_bits[(size_t)(r0 + rl) * NWORDS + (j >> 5)];
                if ((word >> (j & 31)) & 1u) {
                    float4 jd = g_jdata[j];
                    float4 rp = rp_s[rl];
                    float p = (jd.x > rp.x) ? rp.y * jd.y : rp.z * jd.z;
                    w = fmaxf(0.f, p - jd.w);
                }
            }
            w_s[rl][jj] = w;
            unsigned bm = __ballot_sync(0xffffffffu, w > 0.f);
            if ((t & 31) == 0 && bm)
                atomicOr(&nz_s[rl & 3][jj >> 5], bm);
        }
        __syncthreads();
        // ---- sparse accumulate (warp-uniform rowgroup -> no divergence) ----
#pragma unroll
        for (int wd = 0; wd < 4; wd++) {
            unsigned m = nz_s[rg][wd];
            while (m) {
                int b = __ffs(m) - 1;
                m &= m - 1;
                int jj = wd * 32 + b;
                int j = jb + jj;
                float wh = g_Wh[(size_t)j * OUTF + c];
                acc0 = fmaf(w_s[rg + 0][jj],  wh, acc0);
                acc1 = fmaf(w_s[rg + 4][jj],  wh, acc1);
                acc2 = fmaf(w_s[rg + 8][jj],  wh, acc2);
                acc3 = fmaf(w_s[rg + 12][jj], wh, acc3);
            }
        }
    }
    float a;
    a = acc0; out[(size_t)(r0 + rg + 0)  * OUTF + c] = a > 0.f ? a : expm1f(a);
    a = acc1; out[(size_t)(r0 + rg + 4)  * OUTF + c] = a > 0.f ? a : expm1f(a);
    a = acc2; out[(size_t)(r0 + rg + 8)  * OUTF + c] = a > 0.f ? a : expm1f(a);
    a = acc3; out[(size_t)(r0 + rg + 12) * OUTF + c] = a > 0.f ? a : expm1f(a);
}

// ---------------------------------------------------------------------------
extern "C" void kernel_launch(void* const* d_in, const int* in_sizes, int n_in,
                              void* d_out, int out_size) {
    const float* h = nullptr; const float* W = nullptr;
    const float* a_src = nullptr; const float* a_dst = nullptr;
    const float* hub = nullptr; const int* adj = nullptr;
    int a_count = 0;
    for (int i = 0; i < n_in; i++) {
        int s = in_sizes[i];
        if (s == NN * INF_)      h = (const float*)d_in[i];
        else if (s == INF_ * OUTF) W = (const float*)d_in[i];
        else if (s == OUTF) { if (a_count++ == 0) a_src = (const float*)d_in[i];
                              else                a_dst = (const float*)d_in[i]; }
        else if (s == NN)        hub = (const float*)d_in[i];
        else if (s == NN * NN)   adj = (const int*)d_in[i];
    }

    k_gemm<<<1250, 256>>>(h, W, a_src, a_dst, hub);
    k_scan<<<1250, 256>>>(adj);
    k_row<<<(NN + 255) / 256, 256>>>();
    k_agg<<<625, 256>>>((float*)d_out);
}

// round 2
// speedup vs baseline: 2.5321x; 2.5321x over previous
#include <cuda_runtime.h>
#include <math.h>

#define NN 10000
#define NJP 10240          // padded j-count (float4-safe)
#define NV 2500            // NN/4 nibbles per row
#define OUTF 64
#define SMAX 10016         // per-row survivor capacity (>= NN impossible to overflow)
#define LN001 (-4.605170185988091f)
#define EPS_SL 0.02f       // log-domain slack for candidate screen

// ---- static scratch ----
__device__ float g_Wh[NN * OUTF];
__device__ float g_esrc[NN];
__device__ float g_ed[NJP];
__device__ float g_bp[NJP];     // exp(ed - E)
__device__ float g_bn[NJP];     // exp(0.2*(ed - E))
__device__ float g_hT[NJP];     // hub * 0.01
__device__ float g_kA[NJP];     // ed - ln(hub)
__device__ float g_kB[NJP];     // ed - 5*ln(hub)
__device__ float g_E;
__device__ unsigned char g_nib[(size_t)NN * NV];
__device__ float g_Sp[NN], g_Sn[NN];
__device__ float4 g_rowp[NN];   // {ns=-esrc, rpy, rpz, -}
__device__ float4 g_rowt[NN];   // {TA, TB, c, -}
__device__ int g_cnt[NN];
__device__ unsigned short g_sj[(size_t)NN * SMAX];
__device__ float g_sw[(size_t)NN * SMAX];

// ---------------------------------------------------------------------------
// K1: Wh = h @ W (warp per row) + e_src/e_dst dot products
// ---------------------------------------------------------------------------
__global__ void k_gemm(const float* __restrict__ h, const float* __restrict__ W,
                       const float* __restrict__ a_src, const float* __restrict__ a_dst) {
    int warp = threadIdx.x >> 5, lane = threadIdx.x & 31;
    int row = blockIdx.x * 8 + warp;
    if (row >= NN) return;
    const float* hrow = h + (size_t)row * 512;
    float ax = 0.f, ay = 0.f;
    int c2 = lane * 2;
    for (int kb = 0; kb < 512; kb += 32) {
        float hk = hrow[kb + lane];
#pragma unroll
        for (int q = 0; q < 32; q++) {
            float hb = __shfl_sync(0xffffffffu, hk, q);
            float2 w = *reinterpret_cast<const float2*>(W + (size_t)(kb + q) * OUTF + c2);
            ax = fmaf(hb, w.x, ax);
            ay = fmaf(hb, w.y, ay);
        }
    }
    float2 o; o.x = ax; o.y = ay;
    *reinterpret_cast<float2*>(g_Wh + (size_t)row * OUTF + c2) = o;
    float s = ax * a_src[c2] + ay * a_src[c2 + 1];
    float d = ax * a_dst[c2] + ay * a_dst[c2 + 1];
#pragma unroll
    for (int o2 = 16; o2; o2 >>= 1) {
        s += __shfl_xor_sync(0xffffffffu, s, o2);
        d += __shfl_xor_sync(0xffffffffu, d, o2);
    }
    if (lane == 0) { g_esrc[row] = s; g_ed[row] = d; }
}

// ---------------------------------------------------------------------------
// K2: E = max_j ed_j (single block)
// ---------------------------------------------------------------------------
__global__ void k_max() {
    __shared__ float sm[32];
    int t = threadIdx.x;
    float m = -3.0e38f;
    for (int i = t; i < NN; i += 1024) m = fmaxf(m, g_ed[i]);
#pragma unroll
    for (int o = 16; o; o >>= 1) m = fmaxf(m, __shfl_xor_sync(0xffffffffu, m, o));
    if ((t & 31) == 0) sm[t >> 5] = m;
    __syncthreads();
    if (t < 32) {
        m = sm[t];
#pragma unroll
        for (int o = 16; o; o >>= 1) m = fmaxf(m, __shfl_xor_sync(0xffffffffu, m, o));
        if (t == 0) g_E = m;
    }
}

// ---------------------------------------------------------------------------
// K3: per-j tables
// ---------------------------------------------------------------------------
__global__ void k_jtab(const float* __restrict__ hub) {
    int i = blockIdx.x * 256 + threadIdx.x;
    if (i >= NJP) return;
    if (i < NN) {
        float ed = g_ed[i], E = g_E;
        g_bp[i] = expf(ed - E);
        g_bn[i] = expf(0.2f * (ed - E));
        float hb = hub[i];
        float lh = logf(hb);            // hub=0 -> -inf: keys -> +inf (always candidate), correct
        g_hT[i] = hb * 0.01f;
        g_kA[i] = ed - lh;
        g_kB[i] = ed - 5.0f * lh;
    } else {
        g_bp[i] = 0.f; g_bn[i] = 0.f; g_hT[i] = 3.0e38f;
        g_kA[i] = -3.0e38f; g_kB[i] = -3.0e38f; g_ed[i < NJP ? i : 0] = g_ed[i < NJP ? i : 0];
        g_ed[i] = 0.f;
    }
}

// ---------------------------------------------------------------------------
// K4: adj scan — nibble bitmask + Sp/Sn per row. 8 rows/block, int4 loads.
// ---------------------------------------------------------------------------
__global__ void k_scan(const int* __restrict__ adj) {
    int t = threadIdx.x, warp = t >> 5;
    int r0 = blockIdx.x * 8;
    float ns[8], sp[8], sn[8];
#pragma unroll
    for (int r = 0; r < 8; r++) { ns[r] = -g_esrc[r0 + r]; sp[r] = 0.f; sn[r] = 0.f; }

    const float4* ed4p = reinterpret_cast<const float4*>(g_ed);
    const float4* bp4p = reinterpret_cast<const float4*>(g_bp);
    const float4* bn4p = reinterpret_cast<const float4*>(g_bn);

    for (int v = t; v < NV; v += 256) {
        float4 e4 = ed4p[v];
        float4 p4 = bp4p[v];
        float4 n4 = bn4p[v];
        int4 a[8];
#pragma unroll
        for (int r = 0; r < 8; r++)
            a[r] = reinterpret_cast<const int4*>(adj)[(size_t)(r0 + r) * NV + v];
#pragma unroll
        for (int r = 0; r < 8; r++) {
            int4 av = a[r];
            unsigned nib = (av.x > 0 ? 1u : 0u) | (av.y > 0 ? 2u : 0u)
                         | (av.z > 0 ? 4u : 0u) | (av.w > 0 ? 8u : 0u);
            g_nib[(size_t)(r0 + r) * NV + v] = (unsigned char)nib;
            float nsr = ns[r];
            bool o0 = av.x > 0, o1 = av.y > 0, o2 = av.z > 0, o3 = av.w > 0;
            bool q0 = e4.x > nsr, q1 = e4.y > nsr, q2 = e4.z > nsr, q3 = e4.w > nsr;
            sp[r] += ((o0 && q0) ? p4.x : 0.f) + ((o1 && q1) ? p4.y : 0.f)
                   + ((o2 && q2) ? p4.z : 0.f) + ((o3 && q3) ? p4.w : 0.f);
            sn[r] += ((o0 && !q0) ? n4.x : 0.f) + ((o1 && !q1) ? n4.y : 0.f)
                   + ((o2 && !q2) ? n4.z : 0.f) + ((o3 && !q3) ? n4.w : 0.f);
        }
    }
    __shared__ float ssp[8][8], ssn[8][8];
#pragma unroll
    for (int r = 0; r < 8; r++) {
        float b = sp[r], c = sn[r];
#pragma unroll
        for (int o = 16; o; o >>= 1) {
            b += __shfl_xor_sync(0xffffffffu, b, o);
            c += __shfl_xor_sync(0xffffffffu, c, o);
        }
        if ((t & 31) == 0) { ssp[r][warp] = b; ssn[r][warp] = c; }
    }
    __syncthreads();
    if (t < 8) {
        float b = ssp[t][0], c = ssn[t][0];
#pragma unroll
        for (int w = 1; w < 8; w++) { b += ssp[t][w]; c += ssn[t][w]; }
        g_Sp[r0 + t] = b; g_Sn[r0 + t] = c;
    }
}

// ---------------------------------------------------------------------------
// K5: per-row softmax params + prune thresholds
// ---------------------------------------------------------------------------
__global__ void k_row() {
    int i = blockIdx.x * 256 + threadIdx.x;
    if (i >= NN) return;
    float es = g_esrc[i], E = g_E;
    float x = es + E;
    float m = x > 0.f ? x : 0.2f * x;
    float cpE = expf(x - m);              // exp(es + E - m)
    float cnE = expf(0.2f * x - m);       // exp(0.2es + 0.2E - m)
    float s = cpE * g_Sp[i] + cnE * g_Sn[i];
    float inv = 1.0f / s;
    float4 rp; rp.x = -es; rp.y = cpE * inv; rp.z = cnE * inv; rp.w = 0.f;
    g_rowp[i] = rp;
    float L = m + logf(s) + LN001;
    float4 rt;
    rt.x = L - es - EPS_SL;               // TA
    rt.y = 5.0f * L - es - EPS_SL;        // TB
    rt.z = -4.0f * L;                     // caseA iff (kA-kB) > c
    rt.w = 0.f;
    g_rowt[i] = rt;
}

// ---------------------------------------------------------------------------
// K6: prune — emit per-row survivor CSR (j, w). Warp per row.
// ---------------------------------------------------------------------------
__global__ void k_prune() {
    int lane = threadIdx.x & 31;
    int row = blockIdx.x * 8 + (threadIdx.x >> 5);
    float4 rt = g_rowt[row];
    float4 rp = g_rowp[row];
    float TA = rt.x, TB = rt.y, cc = rt.z;
    float nsr = rp.x, rpy = rp.y, rpz = rp.z;
    const unsigned char* nrow = g_nib + (size_t)row * NV;
    const float4* kA4p = reinterpret_cast<const float4*>(g_kA);
    const float4* kB4p = reinterpret_cast<const float4*>(g_kB);
    size_t base = (size_t)row * SMAX;
    int cnt = 0;

    for (int i0 = 0; i0 < NV; i0 += 32) {
        int v = i0 + lane;
        unsigned nib = (v < NV) ? (unsigned)nrow[v] : 0u;
        float4 kA4 = kA4p[v];   // padded to NJP: safe
        float4 kB4 = kB4p[v];
        float d0 = kA4.x - kB4.x, d1 = kA4.y - kB4.y;
        float d2 = kA4.z - kB4.z, d3 = kA4.w - kB4.w;
#pragma unroll
        for (int q = 0; q < 4; q++) {
            float ka = q == 0 ? kA4.x : q == 1 ? kA4.y : q == 2 ? kA4.z : kA4.w;
            float kb = q == 0 ? kB4.x : q == 1 ? kB4.y : q == 2 ? kB4.z : kB4.w;
            float dd = q == 0 ? d0 : q == 1 ? d1 : q == 2 ? d2 : d3;
            bool caseA = dd > cc;
            float key = caseA ? ka : kb;
            float thr = caseA ? TA : TB;
            bool cand = ((nib >> q) & 1u) && (key > thr);
            unsigned bm = __ballot_sync(0xffffffffu, cand);
            if (bm) {
                float w = 0.f;
                int j = v * 4 + q;
                if (cand) {
                    float ed = g_ed[j];
                    float p = (ed > nsr) ? rpy * g_bp[j] : rpz * g_bn[j];
                    w = p - g_hT[j];
                }
                unsigned sm2 = __ballot_sync(0xffffffffu, w > 0.f);
                if (w > 0.f) {
                    int off = cnt + __popc(sm2 & ((1u << lane) - 1u));
                    g_sj[base + off] = (unsigned short)j;
                    g_sw[base + off] = w;
                }
                cnt += __popc(sm2);
            }
        }
    }
    if (lane == 0) g_cnt[row] = cnt;
}

// ---------------------------------------------------------------------------
// K7: sparse SpMM + ELU. Warp per row, lane covers 2 cols (float2).
// ---------------------------------------------------------------------------
__global__ void k_out(float* __restrict__ out) {
    int lane = threadIdx.x & 31;
    int row = blockIdx.x * 8 + (threadIdx.x >> 5);
    int n = g_cnt[row];
    size_t base = (size_t)row * SMAX;
    const float2* whb = reinterpret_cast<const float2*>(g_Wh);
    float ax = 0.f, ay = 0.f;
    for (int s0 = 0; s0 < n; s0 += 32) {
        int idx = s0 + lane;
        int jj = 0; float ww = 0.f;
        if (idx < n) { jj = g_sj[base + idx]; ww = g_sw[base + idx]; }
#pragma unroll
        for (int kk = 0; kk < 32; kk++) {
            int j = __shfl_sync(0xffffffffu, jj, kk);
            float w = __shfl_sync(0xffffffffu, ww, kk);
            float2 wh = whb[(size_t)j * 32 + lane];
            ax = fmaf(w, wh.x, ax);
            ay = fmaf(w, wh.y, ay);
        }
    }
    float2 o;
    o.x = ax > 0.f ? ax : expm1f(ax);
    o.y = ay > 0.f ? ay : expm1f(ay);
    reinterpret_cast<float2*>(out)[(size_t)row * 32 + lane] = o;
}

// ---------------------------------------------------------------------------
extern "C" void kernel_launch(void* const* d_in, const int* in_sizes, int n_in,
                              void* d_out, int out_size) {
    const float* h = nullptr; const float* W = nullptr;
    const float* a_src = nullptr; const float* a_dst = nullptr;
    const float* hub = nullptr; const int* adj = nullptr;
    int a_count = 0;
    for (int i = 0; i < n_in; i++) {
        int s = in_sizes[i];
        if (s == NN * 512)       h = (const float*)d_in[i];
        else if (s == 512 * OUTF) W = (const float*)d_in[i];
        else if (s == OUTF) { if (a_count++ == 0) a_src = (const float*)d_in[i];
                              else                a_dst = (const float*)d_in[i]; }
        else if (s == NN)        hub = (const float*)d_in[i];
        else if (s == NN * NN)   adj = (const int*)d_in[i];
    }

    k_gemm<<<1250, 256>>>(h, W, a_src, a_dst);
    k_max<<<1, 1024>>>();
    k_jtab<<<(NJP + 255) / 256, 256>>>(hub);
    k_scan<<<1250, 256>>>(adj);
    k_row<<<(NN + 255) / 256, 256>>>();
    k_prune<<<1250, 256>>>();
    k_out<<<1250, 256>>>((float*)d_out);
}

// round 3
// speedup vs baseline: 2.8003x; 1.1059x over previous
#include <cuda_runtime.h>
#include <math.h>

#define NN 10000
#define NJP 10240
#define NV 2500
#define OUTF 64
#define SMAX 10016
#define LN001 (-4.605170185988091f)
#define EPS_SL 0.02f

// ---- static scratch ----
__device__ float  g_Wh[NN * OUTF];
__device__ float  g_esrc[NN];
__device__ float  g_ed[NN];
__device__ int    g_Emax;
__device__ float4 g_jd[NJP];         // {ed, bp=exp(ed-E), bn=exp(.2(ed-E)), hub*0.01}
__device__ float2 g_kab[NJP];        // {kA = ed - ln h, kB = ed - 5 ln h}
__device__ float  g_tp[NJP];         // ed   (for scan, contiguous float4 view)
__device__ float  g_tbp[NJP];
__device__ float  g_tbn[NJP];
__device__ unsigned char g_nib[(size_t)NN * NV];
__device__ float  g_Sp[NN], g_Sn[NN];
__device__ float4 g_rowp[NN];        // {ns=-esrc, rpy, rpz, -}
__device__ float4 g_rowt[NN];        // {TA, TB, cc, -}
__device__ int    g_cnt[NN];
__device__ unsigned short g_sj[(size_t)NN * SMAX];
__device__ float  g_sw[(size_t)NN * SMAX];

// float -> order-preserving int key
__device__ __forceinline__ int fkey(float x) {
    int ix = __float_as_int(x);
    return ix >= 0 ? ix : (ix ^ 0x7fffffff);
}
__device__ __forceinline__ float funkey(int k) {
    return __int_as_float(k >= 0 ? k : (k ^ 0x7fffffff));
}

// ---------------------------------------------------------------------------
// K1: Wh = h @ W, smem-tiled: 64 rows x 64 cols per block, 256 threads,
// thread computes 4x4. No shuffles.
// ---------------------------------------------------------------------------
__global__ void k_gemm(const float* __restrict__ h, const float* __restrict__ W) {
    __shared__ float h_s[64][33];
    __shared__ float W_s[32][64];
    int tid = threadIdx.x;
    if (tid == 0 && blockIdx.x == 0) g_Emax = 0x80000000;
    int tx = tid & 15, ty = tid >> 4;
    int gr0 = blockIdx.x * 64;
    float acc[4][4];
#pragma unroll
    for (int i = 0; i < 4; i++)
#pragma unroll
        for (int j = 0; j < 4; j++) acc[i][j] = 0.f;

    for (int k0 = 0; k0 < 512; k0 += 32) {
        __syncthreads();
        // stage h: 64 rows x 32 k (as float4 along k)
#pragma unroll
        for (int it = 0; it < 2; it++) {
            int idx = it * 256 + tid;
            int row = idx >> 3, q = idx & 7;
            float4 h4 = make_float4(0.f, 0.f, 0.f, 0.f);
            if (gr0 + row < NN)
                h4 = *reinterpret_cast<const float4*>(h + (size_t)(gr0 + row) * 512 + k0 + q * 4);
            h_s[row][q * 4 + 0] = h4.x; h_s[row][q * 4 + 1] = h4.y;
            h_s[row][q * 4 + 2] = h4.z; h_s[row][q * 4 + 3] = h4.w;
        }
        // stage W: 32 k x 64 cols
#pragma unroll
        for (int it = 0; it < 2; it++) {
            int idx = it * 256 + tid;
            int kk = idx >> 4, c4 = (idx & 15) * 4;
            float4 w4 = *reinterpret_cast<const float4*>(W + (size_t)(k0 + kk) * OUTF + c4);
            *reinterpret_cast<float4*>(&W_s[kk][c4]) = w4;
        }
        __syncthreads();
#pragma unroll
        for (int kk = 0; kk < 32; kk++) {
            float4 wv = *reinterpret_cast<const float4*>(&W_s[kk][tx * 4]);
            float hv0 = h_s[ty * 4 + 0][kk];
            float hv1 = h_s[ty * 4 + 1][kk];
            float hv2 = h_s[ty * 4 + 2][kk];
            float hv3 = h_s[ty * 4 + 3][kk];
            acc[0][0] = fmaf(hv0, wv.x, acc[0][0]); acc[0][1] = fmaf(hv0, wv.y, acc[0][1]);
            acc[0][2] = fmaf(hv0, wv.z, acc[0][2]); acc[0][3] = fmaf(hv0, wv.w, acc[0][3]);
            acc[1][0] = fmaf(hv1, wv.x, acc[1][0]); acc[1][1] = fmaf(hv1, wv.y, acc[1][1]);
            acc[1][2] = fmaf(hv1, wv.z, acc[1][2]); acc[1][3] = fmaf(hv1, wv.w, acc[1][3]);
            acc[2][0] = fmaf(hv2, wv.x, acc[2][0]); acc[2][1] = fmaf(hv2, wv.y, acc[2][1]);
            acc[2][2] = fmaf(hv2, wv.z, acc[2][2]); acc[2][3] = fmaf(hv2, wv.w, acc[2][3]);
            acc[3][0] = fmaf(hv3, wv.x, acc[3][0]); acc[3][1] = fmaf(hv3, wv.y, acc[3][1]);
            acc[3][2] = fmaf(hv3, wv.z, acc[3][2]); acc[3][3] = fmaf(hv3, wv.w, acc[3][3]);
        }
    }
#pragma unroll
    for (int i = 0; i < 4; i++) {
        int row = gr0 + ty * 4 + i;
        if (row < NN) {
            float4 o; o.x = acc[i][0]; o.y = acc[i][1]; o.z = acc[i][2]; o.w = acc[i][3];
            *reinterpret_cast<float4*>(g_Wh + (size_t)row * OUTF + tx * 4) = o;
        }
    }
}

// ---------------------------------------------------------------------------
// K2: edge dots per row + global atomicMax of e_dst. Warp per row.
// ---------------------------------------------------------------------------
__global__ void k_edot(const float* __restrict__ a_src, const float* __restrict__ a_dst) {
    int lane = threadIdx.x & 31;
    int row = blockIdx.x * 8 + (threadIdx.x >> 5);
    float w0 = g_Wh[(size_t)row * OUTF + lane];
    float w1 = g_Wh[(size_t)row * OUTF + lane + 32];
    float s = w0 * a_src[lane] + w1 * a_src[lane + 32];
    float d = w0 * a_dst[lane] + w1 * a_dst[lane + 32];
#pragma unroll
    for (int o = 16; o; o >>= 1) {
        s += __shfl_xor_sync(0xffffffffu, s, o);
        d += __shfl_xor_sync(0xffffffffu, d, o);
    }
    if (lane == 0) {
        g_esrc[row] = s;
        g_ed[row] = d;
        atomicMax(&g_Emax, fkey(d));
    }
}

// ---------------------------------------------------------------------------
// K3: per-j tables
// ---------------------------------------------------------------------------
__global__ void k_jtab(const float* __restrict__ hub) {
    int i = blockIdx.x * 256 + threadIdx.x;
    if (i >= NJP) return;
    if (i < NN) {
        float E = funkey(g_Emax);
        float ed = g_ed[i];
        float bp = expf(ed - E);
        float bn = expf(0.2f * (ed - E));
        float hb = hub[i];
        float lh = logf(hb);
        float4 jd; jd.x = ed; jd.y = bp; jd.z = bn; jd.w = hb * 0.01f;
        g_jd[i] = jd;
        float2 kb; kb.x = ed - lh; kb.y = ed - 5.0f * lh;
        g_kab[i] = kb;
        g_tp[i] = ed; g_tbp[i] = bp; g_tbn[i] = bn;
    } else {
        float4 jd; jd.x = 0.f; jd.y = 0.f; jd.z = 0.f; jd.w = 3.0e38f;
        g_jd[i] = jd;
        float2 kb; kb.x = -3.0e38f; kb.y = -3.0e38f;
        g_kab[i] = kb;
        g_tp[i] = 0.f; g_tbp[i] = 0.f; g_tbn[i] = 0.f;
    }
}

// ---------------------------------------------------------------------------
// K4: adj scan — nibble bitmask + Sp/Sn. 8 rows/block, streaming int4 loads.
// ---------------------------------------------------------------------------
__global__ void __launch_bounds__(256, 5) k_scan(const int* __restrict__ adj) {
    int t = threadIdx.x, warp = t >> 5;
    int r0 = blockIdx.x * 8;
    float ns[8], sp[8], sn[8];
#pragma unroll
    for (int r = 0; r < 8; r++) { ns[r] = -g_esrc[r0 + r]; sp[r] = 0.f; sn[r] = 0.f; }

    const float4* ed4p = reinterpret_cast<const float4*>(g_tp);
    const float4* bp4p = reinterpret_cast<const float4*>(g_tbp);
    const float4* bn4p = reinterpret_cast<const float4*>(g_tbn);
    const int4*   adj4 = reinterpret_cast<const int4*>(adj);

    for (int v = t; v < NV; v += 256) {
        float4 e4 = ed4p[v];
        float4 p4 = bp4p[v];
        float4 n4 = bn4p[v];
#pragma unroll
        for (int r = 0; r < 8; r++) {
            int4 av = __ldcs(&adj4[(size_t)(r0 + r) * NV + v]);
            bool o0 = av.x > 0, o1 = av.y > 0, o2 = av.z > 0, o3 = av.w > 0;
            unsigned nib = (o0 ? 1u : 0u) | (o1 ? 2u : 0u) | (o2 ? 4u : 0u) | (o3 ? 8u : 0u);
            g_nib[(size_t)(r0 + r) * NV + v] = (unsigned char)nib;
            float nsr = ns[r];
            bool q0 = e4.x > nsr, q1 = e4.y > nsr, q2 = e4.z > nsr, q3 = e4.w > nsr;
            sp[r] += ((o0 && q0) ? p4.x : 0.f) + ((o1 && q1) ? p4.y : 0.f)
                   + ((o2 && q2) ? p4.z : 0.f) + ((o3 && q3) ? p4.w : 0.f);
            sn[r] += ((o0 && !q0) ? n4.x : 0.f) + ((o1 && !q1) ? n4.y : 0.f)
                   + ((o2 && !q2) ? n4.z : 0.f) + ((o3 && !q3) ? n4.w : 0.f);
        }
    }
    __shared__ float ssp[8][8], ssn[8][8];
#pragma unroll
    for (int r = 0; r < 8; r++) {
        float b = sp[r], c = sn[r];
#pragma unroll
        for (int o = 16; o; o >>= 1) {
            b += __shfl_xor_sync(0xffffffffu, b, o);
            c += __shfl_xor_sync(0xffffffffu, c, o);
        }
        if ((t & 31) == 0) { ssp[r][warp] = b; ssn[r][warp] = c; }
    }
    __syncthreads();
    if (t < 8) {
        float b = ssp[t][0], c = ssn[t][0];
#pragma unroll
        for (int w = 1; w < 8; w++) { b += ssp[t][w]; c += ssn[t][w]; }
        g_Sp[r0 + t] = b; g_Sn[r0 + t] = c;
    }
}

// ---------------------------------------------------------------------------
// K5: per-row softmax params + prune thresholds
// ---------------------------------------------------------------------------
__global__ void k_row() {
    int i = blockIdx.x * 256 + threadIdx.x;
    if (i >= NN) return;
    float es = g_esrc[i], E = funkey(g_Emax);
    float x = es + E;
    float m = x > 0.f ? x : 0.2f * x;
    float cpE = expf(x - m);
    float cnE = expf(0.2f * x - m);
    float s = cpE * g_Sp[i] + cnE * g_Sn[i];
    float inv = 1.0f / s;
    float4 rp; rp.x = -es; rp.y = cpE * inv; rp.z = cnE * inv; rp.w = 0.f;
    g_rowp[i] = rp;
    float L = m + logf(s) + LN001;
    float4 rt;
    rt.x = L - es - EPS_SL;
    rt.y = 5.0f * L - es - EPS_SL;
    rt.z = -4.0f * L;
    rt.w = 0.f;
    g_rowt[i] = rt;
}

// ---------------------------------------------------------------------------
// K6: prune — survivor CSR. Warp per row, single any-ballot per v.
// ---------------------------------------------------------------------------
__global__ void k_prune() {
    int lane = threadIdx.x & 31;
    int row = blockIdx.x * 8 + (threadIdx.x >> 5);
    float4 rt = g_rowt[row];
    float4 rp = g_rowp[row];
    float TA = rt.x, TB = rt.y, cc = rt.z;
    float nsr = rp.x, rpy = rp.y, rpz = rp.z;
    const unsigned char* nrow = g_nib + (size_t)row * NV;
    const float4* kab4 = reinterpret_cast<const float4*>(g_kab);
    size_t base = (size_t)row * SMAX;
    int cnt = 0;

    for (int i0 = 0; i0 < NV; i0 += 32) {
        int v = i0 + lane;
        unsigned nib = (v < NV) ? (unsigned)nrow[v] : 0u;
        float4 ab0 = kab4[2 * v];       // {kA0,kB0,kA1,kB1}
        float4 ab1 = kab4[2 * v + 1];   // {kA2,kB2,kA3,kB3}
        unsigned mc = 0;
        {
            bool cA;
            cA = (ab0.x - ab0.y) > cc;
            if ((nib & 1u) && (cA ? (ab0.x > TA) : (ab0.y > TB))) mc |= 1u;
            cA = (ab0.z - ab0.w) > cc;
            if ((nib & 2u) && (cA ? (ab0.z > TA) : (ab0.w > TB))) mc |= 2u;
            cA = (ab1.x - ab1.y) > cc;
            if ((nib & 4u) && (cA ? (ab1.x > TA) : (ab1.y > TB))) mc |= 4u;
            cA = (ab1.z - ab1.w) > cc;
            if ((nib & 8u) && (cA ? (ab1.z > TA) : (ab1.w > TB))) mc |= 8u;
        }
        unsigned anyb = __ballot_sync(0xffffffffu, mc != 0u);
        if (anyb) {
            int nk = 0; int jl[4]; float wl[4];
            while (mc) {
                int q = __ffs(mc) - 1; mc &= mc - 1;
                int j = v * 4 + q;
                float4 jd = g_jd[j];
                float p = (jd.x > nsr) ? rpy * jd.y : rpz * jd.z;
                float w = p - jd.w;
                if (w > 0.f) { jl[nk] = j; wl[nk] = w; nk++; }
            }
            // warp exclusive scan of nk
            int off = nk;
#pragma unroll
            for (int d = 1; d < 32; d <<= 1) {
                int n2 = __shfl_up_sync(0xffffffffu, off, d);
                if (lane >= d) off += n2;
            }
            int tot = __shfl_sync(0xffffffffu, off, 31);
            int excl = off - nk;
            for (int u = 0; u < nk; u++) {
                g_sj[base + cnt + excl + u] = (unsigned short)jl[u];
                g_sw[base + cnt + excl + u] = wl[u];
            }
            cnt += tot;
        }
    }
    if (lane == 0) g_cnt[row] = cnt;
}

// ---------------------------------------------------------------------------
// K7: sparse SpMM + ELU. Warp per row, lane covers 2 cols.
// ---------------------------------------------------------------------------
__global__ void k_out(float* __restrict__ out) {
    int lane = threadIdx.x & 31;
    int row = blockIdx.x * 8 + (threadIdx.x >> 5);
    int n = g_cnt[row];
    size_t base = (size_t)row * SMAX;
    const float2* whb = reinterpret_cast<const float2*>(g_Wh);
    float ax = 0.f, ay = 0.f;
    for (int s0 = 0; s0 < n; s0 += 32) {
        int idx = s0 + lane;
        int jj = 0; float ww = 0.f;
        if (idx < n) { jj = g_sj[base + idx]; ww = g_sw[base + idx]; }
#pragma unroll
        for (int kk = 0; kk < 32; kk++) {
            int j = __shfl_sync(0xffffffffu, jj, kk);
            float w = __shfl_sync(0xffffffffu, ww, kk);
            float2 wh = whb[(size_t)j * 32 + lane];
            ax = fmaf(w, wh.x, ax);
            ay = fmaf(w, wh.y, ay);
        }
    }
    float2 o;
    o.x = ax > 0.f ? ax : expm1f(ax);
    o.y = ay > 0.f ? ay : expm1f(ay);
    reinterpret_cast<float2*>(out)[(size_t)row * 32 + lane] = o;
}

// ---------------------------------------------------------------------------
extern "C" void kernel_launch(void* const* d_in, const int* in_sizes, int n_in,
                              void* d_out, int out_size) {
    const float* h = nullptr; const float* W = nullptr;
    const float* a_src = nullptr; const float* a_dst = nullptr;
    const float* hub = nullptr; const int* adj = nullptr;
    int a_count = 0;
    for (int i = 0; i < n_in; i++) {
        int s = in_sizes[i];
        if (s == NN * 512)        h = (const float*)d_in[i];
        else if (s == 512 * OUTF) W = (const float*)d_in[i];
        else if (s == OUTF) { if (a_count++ == 0) a_src = (const float*)d_in[i];
                              else                a_dst = (const float*)d_in[i]; }
        else if (s == NN)         hub = (const float*)d_in[i];
        else if (s == NN * NN)    adj = (const int*)d_in[i];
    }

    k_gemm<<<157, 256>>>(h, W);
    k_edot<<<1250, 256>>>(a_src, a_dst);
    k_jtab<<<(NJP + 255) / 256, 256>>>(hub);
    k_scan<<<1250, 256>>>(adj);
    k_row<<<(NN + 255) / 256, 256>>>();
    k_prune<<<1250, 256>>>();
    k_out<<<1250, 256>>>((float*)d_out);
}

// round 4
// speedup vs baseline: 3.4134x; 1.2189x over previous
#include <cuda_runtime.h>
#include <math.h>

#define NN 10000
#define NJP 10240
#define NV 2500            // NN/4
#define OUTF 64
#define SMAX 10016
#define LN001 (-4.605170185988091f)
#define EPS_SL 0.02f

// ---- static scratch ----
__device__ float  g_Wh[NN * OUTF];
__device__ float  g_esrc[NN];
__device__ int    g_Emax;
__device__ float4 g_jd[NJP];          // {ed, bp, bn, hub*0.01}
__device__ float2 g_keys[NJP];        // {ed, lh=ln(hub)}
__device__ float  g_tp[NJP];          // ed
__device__ float  g_tbp[NJP];         // exp(ed-E)
__device__ float  g_tbn[NJP];         // exp(0.2(ed-E))
__device__ unsigned g_nib4[(size_t)NV * NV];  // [group][v], byte r = nibble of row 4g+r
__device__ float  g_Sp[NN], g_Sn[NN];
__device__ unsigned short g_sj[(size_t)NN * SMAX];
__device__ float  g_sw[(size_t)NN * SMAX];

__device__ __forceinline__ int fkey(float x) {
    int ix = __float_as_int(x);
    return ix >= 0 ? ix : (ix ^ 0x7fffffff);
}
__device__ __forceinline__ float funkey(int k) {
    return __int_as_float(k >= 0 ? k : (k ^ 0x7fffffff));
}

// ---------------------------------------------------------------------------
// K1: Wh = h @ W (64x64 tile, 256 thr, 4x4/thread) + fused edge dots + Emax
// ---------------------------------------------------------------------------
__global__ void k_gemm(const float* __restrict__ h, const float* __restrict__ W,
                       const float* __restrict__ a_src, const float* __restrict__ a_dst) {
    __shared__ float h_s[64][33];
    __shared__ float W_s[32][64];
    __shared__ int bmax;
    int tid = threadIdx.x;
    if (tid == 0) bmax = 0x80000000;
    int tx = tid & 15, ty = tid >> 4;
    int gr0 = blockIdx.x * 64;
    float acc[4][4];
#pragma unroll
    for (int i = 0; i < 4; i++)
#pragma unroll
        for (int j = 0; j < 4; j++) acc[i][j] = 0.f;

    for (int k0 = 0; k0 < 512; k0 += 32) {
        __syncthreads();
#pragma unroll
        for (int it = 0; it < 2; it++) {
            int idx = it * 256 + tid;
            int row = idx >> 3, q = idx & 7;
            float4 h4 = make_float4(0.f, 0.f, 0.f, 0.f);
            if (gr0 + row < NN)
                h4 = *reinterpret_cast<const float4*>(h + (size_t)(gr0 + row) * 512 + k0 + q * 4);
            h_s[row][q * 4 + 0] = h4.x; h_s[row][q * 4 + 1] = h4.y;
            h_s[row][q * 4 + 2] = h4.z; h_s[row][q * 4 + 3] = h4.w;
        }
#pragma unroll
        for (int it = 0; it < 2; it++) {
            int idx = it * 256 + tid;
            int kk = idx >> 4, c4 = (idx & 15) * 4;
            float4 w4 = *reinterpret_cast<const float4*>(W + (size_t)(k0 + kk) * OUTF + c4);
            *reinterpret_cast<float4*>(&W_s[kk][c4]) = w4;
        }
        __syncthreads();
#pragma unroll
        for (int kk = 0; kk < 32; kk++) {
            float4 wv = *reinterpret_cast<const float4*>(&W_s[kk][tx * 4]);
            float hv0 = h_s[ty * 4 + 0][kk];
            float hv1 = h_s[ty * 4 + 1][kk];
            float hv2 = h_s[ty * 4 + 2][kk];
            float hv3 = h_s[ty * 4 + 3][kk];
            acc[0][0] = fmaf(hv0, wv.x, acc[0][0]); acc[0][1] = fmaf(hv0, wv.y, acc[0][1]);
            acc[0][2] = fmaf(hv0, wv.z, acc[0][2]); acc[0][3] = fmaf(hv0, wv.w, acc[0][3]);
            acc[1][0] = fmaf(hv1, wv.x, acc[1][0]); acc[1][1] = fmaf(hv1, wv.y, acc[1][1]);
            acc[1][2] = fmaf(hv1, wv.z, acc[1][2]); acc[1][3] = fmaf(hv1, wv.w, acc[1][3]);
            acc[2][0] = fmaf(hv2, wv.x, acc[2][0]); acc[2][1] = fmaf(hv2, wv.y, acc[2][1]);
            acc[2][2] = fmaf(hv2, wv.z, acc[2][2]); acc[2][3] = fmaf(hv2, wv.w, acc[2][3]);
            acc[3][0] = fmaf(hv3, wv.x, acc[3][0]); acc[3][1] = fmaf(hv3, wv.y, acc[3][1]);
            acc[3][2] = fmaf(hv3, wv.z, acc[3][2]); acc[3][3] = fmaf(hv3, wv.w, acc[3][3]);
        }
    }
    float4 as4 = *reinterpret_cast<const float4*>(a_src + tx * 4);
    float4 ad4 = *reinterpret_cast<const float4*>(a_dst + tx * 4);
#pragma unroll
    for (int i = 0; i < 4; i++) {
        int row = gr0 + ty * 4 + i;
        if (row < NN) {
            float4 o; o.x = acc[i][0]; o.y = acc[i][1]; o.z = acc[i][2]; o.w = acc[i][3];
            *reinterpret_cast<float4*>(g_Wh + (size_t)row * OUTF + tx * 4) = o;
        }
        float ps = acc[i][0] * as4.x + acc[i][1] * as4.y + acc[i][2] * as4.z + acc[i][3] * as4.w;
        float pd = acc[i][0] * ad4.x + acc[i][1] * ad4.y + acc[i][2] * ad4.z + acc[i][3] * ad4.w;
#pragma unroll
        for (int o = 8; o; o >>= 1) {      // reduce across tx (16 lanes)
            ps += __shfl_xor_sync(0xffffffffu, ps, o);
            pd += __shfl_xor_sync(0xffffffffu, pd, o);
        }
        if (tx == 0 && row < NN) {
            g_esrc[row] = ps;
            float2 kk; kk.x = pd; kk.y = 0.f;   // lh filled by k_jtab
            g_keys[row] = kk;                   // stash ed
            atomicMax(&bmax, fkey(pd));
        }
    }
    __syncthreads();
    if (tid == 0) atomicMax(&g_Emax, bmax);
}

// ---------------------------------------------------------------------------
// K2: per-j tables
// ---------------------------------------------------------------------------
__global__ void k_jtab(const float* __restrict__ hub) {
    int i = blockIdx.x * 256 + threadIdx.x;
    if (i >= NJP) return;
    if (i < NN) {
        float E = funkey(g_Emax);
        float ed = g_keys[i].x;
        float bp = expf(ed - E);
        float bn = expf(0.2f * (ed - E));
        float hb = hub[i];
        float lh = logf(hb);
        float4 jd; jd.x = ed; jd.y = bp; jd.z = bn; jd.w = hb * 0.01f;
        g_jd[i] = jd;
        float2 kk; kk.x = ed; kk.y = lh;
        g_keys[i] = kk;
        g_tp[i] = ed; g_tbp[i] = bp; g_tbn[i] = bn;
    } else {
        float2 kk; kk.x = 0.f; kk.y = 1.0e30f;  // G huge -> never candidate
        g_keys[i] = kk;
        g_tp[i] = 0.f; g_tbp[i] = 0.f; g_tbn[i] = 0.f;
        float4 jd; jd.x = 0.f; jd.y = 0.f; jd.z = 0.f; jd.w = 3.0e38f;
        g_jd[i] = jd;
    }
}

// ---------------------------------------------------------------------------
// K3: adj scan — 4 rows (=1 group) per block, packed u32 nibbles, Sp/Sn
// ---------------------------------------------------------------------------
__global__ void __launch_bounds__(256, 5) k_scan(const int* __restrict__ adj) {
    int t = threadIdx.x, warp = t >> 5;
    int grp = blockIdx.x;
    int r0 = grp * 4;
    float ns[4], sp[4], sn[4];
#pragma unroll
    for (int r = 0; r < 4; r++) { ns[r] = -g_esrc[r0 + r]; sp[r] = 0.f; sn[r] = 0.f; }

    const float4* ed4p = reinterpret_cast<const float4*>(g_tp);
    const float4* bp4p = reinterpret_cast<const float4*>(g_tbp);
    const float4* bn4p = reinterpret_cast<const float4*>(g_tbn);
    const int4*   adj4 = reinterpret_cast<const int4*>(adj);
    unsigned* nibrow = g_nib4 + (size_t)grp * NV;

    for (int v = t; v < NV; v += 256) {
        float4 e4 = ed4p[v];
        float4 p4 = bp4p[v];
        float4 n4 = bn4p[v];
        unsigned pack = 0;
#pragma unroll
        for (int r = 0; r < 4; r++) {
            int4 av = __ldcs(&adj4[(size_t)(r0 + r) * NV + v]);
            bool o0 = av.x > 0, o1 = av.y > 0, o2 = av.z > 0, o3 = av.w > 0;
            unsigned nib = (o0 ? 1u : 0u) | (o1 ? 2u : 0u) | (o2 ? 4u : 0u) | (o3 ? 8u : 0u);
            pack |= nib << (8 * r);
            float nsr = ns[r];
            bool q0 = e4.x > nsr, q1 = e4.y > nsr, q2 = e4.z > nsr, q3 = e4.w > nsr;
            sp[r] += ((o0 && q0) ? p4.x : 0.f) + ((o1 && q1) ? p4.y : 0.f)
                   + ((o2 && q2) ? p4.z : 0.f) + ((o3 && q3) ? p4.w : 0.f);
            sn[r] += ((o0 && !q0) ? n4.x : 0.f) + ((o1 && !q1) ? n4.y : 0.f)
                   + ((o2 && !q2) ? n4.z : 0.f) + ((o3 && !q3) ? n4.w : 0.f);
        }
        nibrow[v] = pack;
    }
    __shared__ float ssp[4][8], ssn[4][8];
#pragma unroll
    for (int r = 0; r < 4; r++) {
        float b = sp[r], c = sn[r];
#pragma unroll
        for (int o = 16; o; o >>= 1) {
            b += __shfl_xor_sync(0xffffffffu, b, o);
            c += __shfl_xor_sync(0xffffffffu, c, o);
        }
        if ((t & 31) == 0) { ssp[r][warp] = b; ssn[r][warp] = c; }
    }
    __syncthreads();
    if (t < 4) {
        float b = ssp[t][0], c = ssn[t][0];
#pragma unroll
        for (int w = 1; w < 8; w++) { b += ssp[t][w]; c += ssn[t][w]; }
        g_Sp[r0 + t] = b; g_Sn[r0 + t] = c;
    }
}

// ---------------------------------------------------------------------------
// K4: fused row-params + prune + sparse SpMM + ELU.
// Block = 128 thr = 4 warps = 16 rows. Warp screens 4 rows per key load.
// ---------------------------------------------------------------------------
__global__ void __launch_bounds__(128, 8) k_pruneout(float* __restrict__ out) {
    __shared__ float4 rowp_s[16];   // {L, esE, rpy, rpz}
    __shared__ float  ns_s[16];
    __shared__ int    scnt[16];
    int t = threadIdx.x;
    int R0 = blockIdx.x * 16;
    if (t < 16) {
        int row = R0 + t;
        float es = g_esrc[row], E = funkey(g_Emax);
        float x = es + E;
        float m = x > 0.f ? x : 0.2f * x;
        float cpE = expf(x - m);
        float cnE = expf(0.2f * x - m);
        float s = cpE * g_Sp[row] + cnE * g_Sn[row];
        float inv = 1.0f / s;
        float L = m + logf(s) + LN001;
        float4 rp; rp.x = L; rp.y = es + EPS_SL; rp.z = cpE * inv; rp.w = cnE * inv;
        rowp_s[t] = rp;
        ns_s[t] = -es;
        scnt[t] = 0;
    }
    __syncthreads();
    int lane = t & 31, w = t >> 5;
    int g = blockIdx.x * 4 + w;         // global 4-row group
    float L[4], esE[4], nsr[4], rpy[4], rpz[4];
#pragma unroll
    for (int r = 0; r < 4; r++) {
        float4 rp = rowp_s[w * 4 + r];
        L[r] = rp.x; esE[r] = rp.y; rpy[r] = rp.z; rpz[r] = rp.w;
        nsr[r] = ns_s[w * 4 + r];
    }
    const unsigned* nibrow = g_nib4 + (size_t)g * NV;
    const float4* key4 = reinterpret_cast<const float4*>(g_keys);

    for (int v = lane; v < NV; v += 32) {
        unsigned nb = nibrow[v];
        float4 kk0 = key4[2 * v];        // {ed0,lh0,ed1,lh1}
        float4 kk1 = key4[2 * v + 1];    // {ed2,lh2,ed3,lh3}
        unsigned mc = 0;
#pragma unroll
        for (int r = 0; r < 4; r++) {
            unsigned nr = (nb >> (8 * r)) & 0xFu;
            float Lr = L[r], eE = esE[r];
            float G, tt;
            G = Lr + kk0.y; tt = fminf(G, 5.f * G);
            if ((nr & 1u) && (kk0.x + eE > tt)) mc |= 1u << (r * 4 + 0);
            G = Lr + kk0.w; tt = fminf(G, 5.f * G);
            if ((nr & 2u) && (kk0.z + eE > tt)) mc |= 1u << (r * 4 + 1);
            G = Lr + kk1.y; tt = fminf(G, 5.f * G);
            if ((nr & 4u) && (kk1.x + eE > tt)) mc |= 1u << (r * 4 + 2);
            G = Lr + kk1.w; tt = fminf(G, 5.f * G);
            if ((nr & 8u) && (kk1.z + eE > tt)) mc |= 1u << (r * 4 + 3);
        }
        while (mc) {
            int b = __ffs(mc) - 1; mc &= mc - 1;
            int r = b >> 2, q = b & 3;
            int j = v * 4 + q;
            float4 jd = g_jd[j];
            float p = (jd.x > nsr[r]) ? rpy[r] * jd.y : rpz[r] * jd.z;
            float wv = p - jd.w;
            if (wv > 0.f) {
                int off = atomicAdd(&scnt[w * 4 + r], 1);
                size_t base = (size_t)(R0 + w * 4 + r) * SMAX;
                g_sj[base + off] = (unsigned short)j;
                g_sw[base + off] = wv;
            }
        }
    }
    __syncthreads();
    // ---- SpMM phase: each warp does its 4 rows sequentially ----
    const float2* whb = reinterpret_cast<const float2*>(g_Wh);
#pragma unroll
    for (int rr = 0; rr < 4; rr++) {
        int row = R0 + w * 4 + rr;
        int n = scnt[w * 4 + rr];
        size_t base = (size_t)row * SMAX;
        float ax = 0.f, ay = 0.f;
        int p = 0;
        for (; p + 1 < n; p += 2) {
            int j0 = g_sj[base + p], j1 = g_sj[base + p + 1];
            float w0 = g_sw[base + p], w1 = g_sw[base + p + 1];
            float2 a0 = whb[(size_t)j0 * 32 + lane];
            float2 a1 = whb[(size_t)j1 * 32 + lane];
            ax = fmaf(w0, a0.x, ax); ay = fmaf(w0, a0.y, ay);
            ax = fmaf(w1, a1.x, ax); ay = fmaf(w1, a1.y, ay);
        }
        if (p < n) {
            int j0 = g_sj[base + p];
            float w0 = g_sw[base + p];
            float2 a0 = whb[(size_t)j0 * 32 + lane];
            ax = fmaf(w0, a0.x, ax); ay = fmaf(w0, a0.y, ay);
        }
        float2 o;
        o.x = ax > 0.f ? ax : expm1f(ax);
        o.y = ay > 0.f ? ay : expm1f(ay);
        reinterpret_cast<float2*>(out)[(size_t)row * 32 + lane] = o;
    }
}

// ---------------------------------------------------------------------------
extern "C" void kernel_launch(void* const* d_in, const int* in_sizes, int n_in,
                              void* d_out, int out_size) {
    const float* h = nullptr; const float* W = nullptr;
    const float* a_src = nullptr; const float* a_dst = nullptr;
    const float* hub = nullptr; const int* adj = nullptr;
    int a_count = 0;
    for (int i = 0; i < n_in; i++) {
        int s = in_sizes[i];
        if (s == NN * 512)        h = (const float*)d_in[i];
        else if (s == 512 * OUTF) W = (const float*)d_in[i];
        else if (s == OUTF) { if (a_count++ == 0) a_src = (const float*)d_in[i];
                              else                a_dst = (const float*)d_in[i]; }
        else if (s == NN)         hub = (const float*)d_in[i];
        else if (s == NN * NN)    adj = (const int*)d_in[i];
    }

    void* emax_ptr = nullptr;
    cudaGetSymbolAddress(&emax_ptr, g_Emax);
    cudaMemsetAsync(emax_ptr, 0x80, sizeof(int));   // ~INT_MIN key

    k_gemm<<<157, 256>>>(h, W, a_src, a_dst);
    k_jtab<<<(NJP + 255) / 256, 256>>>(hub);
    k_scan<<<NV, 256>>>(adj);
    k_pruneout<<<625, 128>>>((float*)d_out);
}